// round 5
// baseline (speedup 1.0000x reference)
#include <cuda_runtime.h>

typedef unsigned long long ull;

// ---- packed f32x2 helpers ----
__device__ __forceinline__ ull fma2(ull a, ull b, ull c) {
    ull d; asm("fma.rn.f32x2 %0,%1,%2,%3;" : "=l"(d) : "l"(a), "l"(b), "l"(c)); return d;
}
__device__ __forceinline__ ull pk2(float lo, float hi) {
    ull d; asm("mov.b64 %0,{%1,%2};" : "=l"(d) : "f"(lo), "f"(hi)); return d;
}
__device__ __forceinline__ float ex2(float x) {
    float r; asm("ex2.approx.ftz.f32 %0,%1;" : "=f"(r) : "f"(x)); return r;
}

#define LOG2E 1.4426950408889634f

// ---- folded params in d_P ----
// [0..32) gate W [i*8+e] (log2e), [32..40) gate b (log2e)
// [40..200) expert e*20: EP[i*4+j], epb at +16
// [200..216) RP, [216..220) rpb
// [220..224) dC (log2e), [224] dcb (log2e)
// [232..236) pb
__device__ alignas(16) float d_P[240];
__device__ double           d_acc[16];
__device__ unsigned int     d_count;

// ================= setup: stage weights in shared (float4), then fold =================
__global__ __launch_bounds__(256) void setup_kernel(
    const float* __restrict__ w_embed,  const float* __restrict__ b_embed,
    const float* __restrict__ gate_w,   const float* __restrict__ expert_w,
    const float* __restrict__ expert_b, const float* __restrict__ resid_w,
    const float* __restrict__ resid_b,  const float* __restrict__ comb_w,
    const float* __restrict__ comb_b,   const float* __restrict__ proj_w,
    const float* __restrict__ proj_b)
{
    __shared__ float sE[2048];   // expert_w [e*256 + m*16 + k]
    __shared__ float sR[256];    // resid_w  [m*16+k]
    __shared__ float sG[128];    // gate_w   [m*8+e]
    __shared__ float sW[64];     // w_embed  [i*16+m]
    __shared__ float sPj[64];    // proj_w   [k*4+j]
    __shared__ float sEb[128];   // expert_b [e*16+k]
    __shared__ float sBe[16];    // b_embed
    __shared__ float sRb[16];    // resid_b
    __shared__ float sCw[32];    // comb_w   [m*2+c]

    const int t = threadIdx.x;

    // ---- vectorized staging (all inputs are cudaMalloc'd -> 16B aligned) ----
    {
        const float4* s = (const float4*)expert_w;
        float4* d = (float4*)sE;
        d[t] = s[t];
        d[t + 256] = s[t + 256];
    }
    if (t < 64)       ((float4*)sR)[t]        = ((const float4*)resid_w)[t];
    else if (t < 96)  ((float4*)sG)[t - 64]   = ((const float4*)gate_w)[t - 64];
    else if (t < 112) ((float4*)sW)[t - 96]   = ((const float4*)w_embed)[t - 96];
    else if (t < 128) ((float4*)sPj)[t - 112] = ((const float4*)proj_w)[t - 112];
    else if (t < 160) ((float4*)sEb)[t - 128] = ((const float4*)expert_b)[t - 128];
    else if (t < 164) ((float4*)sBe)[t - 160] = ((const float4*)b_embed)[t - 160];
    else if (t < 168) ((float4*)sRb)[t - 164] = ((const float4*)resid_b)[t - 164];
    else if (t < 176) ((float4*)sCw)[t - 168] = ((const float4*)comb_w)[t - 168];
    __syncthreads();

    // ---- folds from shared ----
    if (t < 128) {                              // EP[e][i][j]
        int e = t >> 4, i = (t >> 2) & 3, j = t & 3;
        float acc = 0.f;
        #pragma unroll
        for (int k = 0; k < 16; k++) {
            float tmp = 0.f;
            #pragma unroll
            for (int m = 0; m < 16; m++)
                tmp = fmaf(sW[i * 16 + m], sE[e * 256 + m * 16 + k], tmp);
            acc = fmaf(tmp, sPj[k * 4 + j], acc);
        }
        d_P[40 + e * 20 + i * 4 + j] = acc;
    } else if (t < 160) {                       // epb[e][j]
        int u = t - 128, e = u >> 2, j = u & 3;
        float acc = 0.f;
        #pragma unroll
        for (int k = 0; k < 16; k++) {
            float tmp = sEb[e * 16 + k];
            #pragma unroll
            for (int m = 0; m < 16; m++)
                tmp = fmaf(sBe[m], sE[e * 256 + m * 16 + k], tmp);
            acc = fmaf(tmp, sPj[k * 4 + j], acc);
        }
        d_P[40 + e * 20 + 16 + j] = acc;
    } else if (t < 176) {                       // RP[i][j]
        int u = t - 160, i = u >> 2, j = u & 3;
        float acc = 0.f;
        #pragma unroll
        for (int k = 0; k < 16; k++) {
            float tmp = 0.f;
            #pragma unroll
            for (int m = 0; m < 16; m++)
                tmp = fmaf(sW[i * 16 + m], sR[m * 16 + k], tmp);
            acc = fmaf(tmp, sPj[k * 4 + j], acc);
        }
        d_P[200 + i * 4 + j] = acc;
    } else if (t < 180) {                       // rpb[j]
        int j = t - 176;
        float acc = 0.f;
        #pragma unroll
        for (int k = 0; k < 16; k++) {
            float tmp = sRb[k];
            #pragma unroll
            for (int m = 0; m < 16; m++)
                tmp = fmaf(sBe[m], sR[m * 16 + k], tmp);
            acc = fmaf(tmp, sPj[k * 4 + j], acc);
        }
        d_P[216 + j] = acc;
    } else if (t < 212) {                       // gate W (log2e)
        int u = t - 180, i = u >> 3, e = u & 7;
        float acc = 0.f;
        #pragma unroll
        for (int m = 0; m < 16; m++)
            acc = fmaf(sW[i * 16 + m], sG[m * 8 + e], acc);
        d_P[i * 8 + e] = acc * LOG2E;
    } else if (t < 220) {                       // gate b (log2e)
        int e = t - 212;
        float acc = 0.f;
        #pragma unroll
        for (int m = 0; m < 16; m++)
            acc = fmaf(sBe[m], sG[m * 8 + e], acc);
        d_P[32 + e] = acc * LOG2E;
    } else if (t < 224) {                       // dC (log2e)
        int i = t - 220;
        float acc = 0.f;
        #pragma unroll
        for (int m = 0; m < 16; m++)
            acc = fmaf(sW[i * 16 + m], sCw[m * 2 + 1] - sCw[m * 2], acc);
        d_P[220 + i] = acc * LOG2E;
    } else if (t == 224) {                      // dcb (log2e)
        float acc = comb_b[1] - comb_b[0];
        #pragma unroll
        for (int m = 0; m < 16; m++)
            acc = fmaf(sBe[m], sCw[m * 2 + 1] - sCw[m * 2], acc);
        d_P[224] = acc * LOG2E;
    } else if (t < 229) {                       // pb
        d_P[232 + (t - 225)] = proj_b[t - 225];
    } else if (t < 245) {                       // zero accumulators (replay-safe)
        d_acc[t - 229] = 0.0;
    } else if (t == 245) {
        d_count = 0u;
    }
}

// ================= main streaming kernel =================
__global__ __launch_bounds__(256, 3) void moe_main_kernel(
    const float4* __restrict__ x4, float4* __restrict__ o4,
    float* __restrict__ out, int n, int out_size)
{
    __shared__ alignas(16) float P[240];
    __shared__ float red[8][16];
    __shared__ unsigned s_last;

    const int t = threadIdx.x;
    if (t < 60) ((float4*)P)[t] = ((const float4*)d_P)[t];
    __syncthreads();

    const ull* Gp  = (const ull*)P;              // gate rows as pairs
    const ull* Rp  = (const ull*)(P + 200);
    const ull Pbp0 = ((const ull*)(P + 232))[0];
    const ull Pbp1 = ((const ull*)(P + 232))[1];
    const float Dc0 = P[220], Dc1 = P[221], Dc2 = P[222], Dc3 = P[223], Dcb = P[224];

    float S[8] = {0.f, 0.f, 0.f, 0.f, 0.f, 0.f, 0.f, 0.f};
    ull cnt = 0;        // 8 byte-counters (tokens/thread <= 255)

    const int stride = blockDim.x * gridDim.x;
    #pragma unroll 2
    for (int i = blockIdx.x * blockDim.x + t; i < n; i += stride) {
        const float4 xv = x4[i];
        const ull xx = pk2(xv.x, xv.x), yy = pk2(xv.y, xv.y);
        const ull zz = pk2(xv.z, xv.z), ww = pk2(xv.w, xv.w);

        // gate logits in log2 domain (4 packed pairs)
        float lg[8];
        #pragma unroll
        for (int k = 0; k < 4; k++) {
            ull v = fma2(xx, Gp[k],      Gp[16 + k]);
            v     = fma2(yy, Gp[4 + k],  v);
            v     = fma2(zz, Gp[8 + k],  v);
            v     = fma2(ww, Gp[12 + k], v);
            float2 f = *(float2*)&v; lg[2 * k] = f.x; lg[2 * k + 1] = f.y;
        }

        // max via tree (depth 3), first-max index via equality mask + ffs
        const float m = fmaxf(fmaxf(fmaxf(lg[0], lg[1]), fmaxf(lg[2], lg[3])),
                              fmaxf(fmaxf(lg[4], lg[5]), fmaxf(lg[6], lg[7])));
        unsigned msk = 0;
        #pragma unroll
        for (int e = 0; e < 8; e++) msk |= (lg[e] == m) ? (1u << e) : 0u;
        const int idx = __ffs(msk) - 1;           // first occurrence == jnp.argmax

        // softmax probs via ex2 (coeffs pre-scaled by log2e)
        float p[8];
        #pragma unroll
        for (int e = 0; e < 8; e++) p[e] = ex2(lg[e] - m);
        const float sum = ((p[0] + p[1]) + (p[2] + p[3])) + ((p[4] + p[5]) + (p[6] + p[7]));
        const float inv = __fdividef(1.f, sum);   // == gates[idx] (ex2(0)=1)
        #pragma unroll
        for (int e = 0; e < 8; e++) S[e] = fmaf(p[e], inv, S[e]);
        cnt += 1ull << (idx << 3);

        // 2-way combine softmax == sigmoid (log2 domain)
        const float dl = fmaf(xv.w, Dc3, fmaf(xv.z, Dc2,
                         fmaf(xv.y, Dc1, fmaf(xv.x, Dc0, Dcb))));
        const float cw0 = __fdividef(1.f, 1.f + ex2(dl));
        const float cw1 = 1.f - cw0;
        const float a   = cw0 * inv;

        // expert block: 5x LDS.128 (80B stride -> conflict-free across idx)
        const ulonglong2* Ep = (const ulonglong2*)(P + 40 + idx * 20);
        const ulonglong2 e0 = Ep[0], e1 = Ep[1], e2 = Ep[2], e3 = Ep[3], e4 = Ep[4];
        ull v01 = fma2(xx, e0.x, e4.x);
        v01 = fma2(yy, e1.x, v01); v01 = fma2(zz, e2.x, v01); v01 = fma2(ww, e3.x, v01);
        ull v23 = fma2(xx, e0.y, e4.y);
        v23 = fma2(yy, e1.y, v23); v23 = fma2(zz, e2.y, v23); v23 = fma2(ww, e3.y, v23);

        // residual (pre-folded thru proj)
        ull r01 = fma2(xx, Rp[0], Rp[8]);
        r01 = fma2(yy, Rp[2], r01); r01 = fma2(zz, Rp[4], r01); r01 = fma2(ww, Rp[6], r01);
        ull r23 = fma2(xx, Rp[1], Rp[9]);
        r23 = fma2(yy, Rp[3], r23); r23 = fma2(zz, Rp[5], r23); r23 = fma2(ww, Rp[7], r23);

        const ull aa = pk2(a, a), cc = pk2(cw1, cw1);
        union { ull u[2]; float4 v; } ou;
        ou.u[0] = fma2(aa, v01, fma2(cc, r01, Pbp0));
        ou.u[1] = fma2(aa, v23, fma2(cc, r23, Pbp1));
        o4[i] = ou.v;
    }

    // ---- aux reduction: warp -> block -> global ----
    float Cf[8];
    #pragma unroll
    for (int e = 0; e < 8; e++) Cf[e] = (float)((cnt >> (e << 3)) & 0xFFull);

    #pragma unroll
    for (int e = 0; e < 8; e++) {
        #pragma unroll
        for (int off = 16; off; off >>= 1) {
            S[e]  += __shfl_down_sync(0xffffffffu, S[e],  off);
            Cf[e] += __shfl_down_sync(0xffffffffu, Cf[e], off);
        }
    }
    const int lane = t & 31, w = t >> 5;
    if (lane == 0) {
        #pragma unroll
        for (int e = 0; e < 8; e++) { red[w][e] = S[e]; red[w][8 + e] = Cf[e]; }
    }
    __syncthreads();
    if (t < 16) {
        float v = 0.f;
        #pragma unroll
        for (int w2 = 0; w2 < 8; w2++) v += red[w2][t];
        atomicAdd(&d_acc[t], (double)v);
        __threadfence();
    }
    __syncthreads();

    // ---- last-block finalize (graph-replay-safe reset) ----
    if (t == 0) {
        unsigned old = atomicAdd(&d_count, 1u);
        s_last = (old == gridDim.x - 1) ? 1u : 0u;
    }
    __syncthreads();
    if (s_last && t == 0) {
        volatile double* acc = d_acc;
        double s = 0.0;
        #pragma unroll
        for (int e = 0; e < 8; e++) s += acc[e] * acc[8 + e];
        if (out_size > n * 4) {
            const double dn = (double)n;
            out[n * 4] = (float)(8.0 * s / (dn * dn));
        }
        #pragma unroll
        for (int k = 0; k < 16; k++) acc[k] = 0.0;
        __threadfence();
        d_count = 0u;
    }
}

extern "C" void kernel_launch(void* const* d_in, const int* in_sizes, int n_in,
                              void* d_out, int out_size)
{
    const float* x        = (const float*)d_in[0];
    const float* w_embed  = (const float*)d_in[1];
    const float* b_embed  = (const float*)d_in[2];
    const float* gate_w   = (const float*)d_in[3];
    const float* expert_w = (const float*)d_in[4];
    const float* expert_b = (const float*)d_in[5];
    const float* resid_w  = (const float*)d_in[6];
    const float* resid_b  = (const float*)d_in[7];
    const float* comb_w   = (const float*)d_in[8];
    const float* comb_b   = (const float*)d_in[9];
    const float* proj_w   = (const float*)d_in[10];
    const float* proj_b   = (const float*)d_in[11];

    const int n = in_sizes[0] / 4;          // tokens

    setup_kernel<<<1, 256>>>(w_embed, b_embed, gate_w, expert_w, expert_b,
                             resid_w, resid_b, comb_w, comb_b, proj_w, proj_b);

    int grid = (n + 256 * 8 - 1) / (256 * 8);   // 8 tokens/thread
    if (grid < 1) grid = 1;

    moe_main_kernel<<<grid, 256>>>((const float4*)x, (float4*)d_out,
                                   (float*)d_out, n, out_size);
}

// round 6
// speedup vs baseline: 1.4699x; 1.4699x over previous
#include <cuda_runtime.h>

__device__ __forceinline__ float ex2(float x) {
    float r; asm("ex2.approx.ftz.f32 %0,%1;" : "=f"(r) : "f"(x)); return r;
}

#define LOG2E 1.4426950408889634f

// ---- folded-parameter layout in d_P / P[256] (R1 layout) ----
// [0..32)    G    gate weights [i*8+e]   (log2e-prescaled)
// [32..40)   gb   gate bias              (log2e-prescaled)
// [40..200)  E    per-expert 20: [e*20 + i*4 + j]=EP(4x4), [e*20+16+j]=epb
// [200..216) RP   resid folded thru proj [i*4+j]
// [216..220) rpb
// [220..224) dC   differenced combine    (log2e-prescaled)
// [224]      dcb                         (log2e-prescaled)
// [230..234) pb   proj bias
__device__ alignas(16) float d_P[256];
__device__ double           d_acc[16];   // [0..8) prob sums, [8..16) argmax counts
__device__ unsigned int     d_count;

// ================= setup: float4-staged weights, direct folds (fast, 1 block) =================
__global__ __launch_bounds__(256) void setup_kernel(
    const float* __restrict__ w_embed,  const float* __restrict__ b_embed,
    const float* __restrict__ gate_w,   const float* __restrict__ expert_w,
    const float* __restrict__ expert_b, const float* __restrict__ resid_w,
    const float* __restrict__ resid_b,  const float* __restrict__ comb_w,
    const float* __restrict__ comb_b,   const float* __restrict__ proj_w,
    const float* __restrict__ proj_b)
{
    __shared__ float sE[2048];   // expert_w [e*256 + m*16 + k]
    __shared__ float sR[256];    // resid_w  [m*16+k]
    __shared__ float sG[128];    // gate_w   [m*8+e]
    __shared__ float sW[64];     // w_embed  [i*16+m]
    __shared__ float sPj[64];    // proj_w   [k*4+j]
    __shared__ float sEb[128];   // expert_b [e*16+k]
    __shared__ float sBe[16];    // b_embed
    __shared__ float sRb[16];    // resid_b
    __shared__ float sCw[32];    // comb_w   [m*2+c]

    const int t = threadIdx.x;

    // vectorized staging (cudaMalloc'd inputs are 16B aligned)
    {
        const float4* s = (const float4*)expert_w;
        float4* d = (float4*)sE;
        d[t] = s[t];
        d[t + 256] = s[t + 256];
    }
    if (t < 64)       ((float4*)sR)[t]        = ((const float4*)resid_w)[t];
    else if (t < 96)  ((float4*)sG)[t - 64]   = ((const float4*)gate_w)[t - 64];
    else if (t < 112) ((float4*)sW)[t - 96]   = ((const float4*)w_embed)[t - 96];
    else if (t < 128) ((float4*)sPj)[t - 112] = ((const float4*)proj_w)[t - 112];
    else if (t < 160) ((float4*)sEb)[t - 128] = ((const float4*)expert_b)[t - 128];
    else if (t < 164) ((float4*)sBe)[t - 160] = ((const float4*)b_embed)[t - 160];
    else if (t < 168) ((float4*)sRb)[t - 164] = ((const float4*)resid_b)[t - 164];
    else if (t < 176) ((float4*)sCw)[t - 168] = ((const float4*)comb_w)[t - 168];
    __syncthreads();

    if (t < 128) {                              // EP[e][i][j]
        int e = t >> 4, i = (t >> 2) & 3, j = t & 3;
        float acc = 0.f;
        #pragma unroll
        for (int k = 0; k < 16; k++) {
            float tmp = 0.f;
            #pragma unroll
            for (int m = 0; m < 16; m++)
                tmp = fmaf(sW[i * 16 + m], sE[e * 256 + m * 16 + k], tmp);
            acc = fmaf(tmp, sPj[k * 4 + j], acc);
        }
        d_P[40 + e * 20 + i * 4 + j] = acc;
    } else if (t < 160) {                       // epb[e][j]
        int u = t - 128, e = u >> 2, j = u & 3;
        float acc = 0.f;
        #pragma unroll
        for (int k = 0; k < 16; k++) {
            float tmp = sEb[e * 16 + k];
            #pragma unroll
            for (int m = 0; m < 16; m++)
                tmp = fmaf(sBe[m], sE[e * 256 + m * 16 + k], tmp);
            acc = fmaf(tmp, sPj[k * 4 + j], acc);
        }
        d_P[40 + e * 20 + 16 + j] = acc;
    } else if (t < 176) {                       // RP[i][j]
        int u = t - 160, i = u >> 2, j = u & 3;
        float acc = 0.f;
        #pragma unroll
        for (int k = 0; k < 16; k++) {
            float tmp = 0.f;
            #pragma unroll
            for (int m = 0; m < 16; m++)
                tmp = fmaf(sW[i * 16 + m], sR[m * 16 + k], tmp);
            acc = fmaf(tmp, sPj[k * 4 + j], acc);
        }
        d_P[200 + i * 4 + j] = acc;
    } else if (t < 180) {                       // rpb[j]
        int j = t - 176;
        float acc = 0.f;
        #pragma unroll
        for (int k = 0; k < 16; k++) {
            float tmp = sRb[k];
            #pragma unroll
            for (int m = 0; m < 16; m++)
                tmp = fmaf(sBe[m], sR[m * 16 + k], tmp);
            acc = fmaf(tmp, sPj[k * 4 + j], acc);
        }
        d_P[216 + j] = acc;
    } else if (t < 212) {                       // gate W (log2e)
        int u = t - 180, i = u >> 3, e = u & 7;
        float acc = 0.f;
        #pragma unroll
        for (int m = 0; m < 16; m++)
            acc = fmaf(sW[i * 16 + m], sG[m * 8 + e], acc);
        d_P[i * 8 + e] = acc * LOG2E;
    } else if (t < 220) {                       // gate b (log2e)
        int e = t - 212;
        float acc = 0.f;
        #pragma unroll
        for (int m = 0; m < 16; m++)
            acc = fmaf(sBe[m], sG[m * 8 + e], acc);
        d_P[32 + e] = acc * LOG2E;
    } else if (t < 224) {                       // dC (log2e)
        int i = t - 220;
        float acc = 0.f;
        #pragma unroll
        for (int m = 0; m < 16; m++)
            acc = fmaf(sW[i * 16 + m], sCw[m * 2 + 1] - sCw[m * 2], acc);
        d_P[220 + i] = acc * LOG2E;
    } else if (t == 224) {                      // dcb (log2e)
        float acc = comb_b[1] - comb_b[0];
        #pragma unroll
        for (int m = 0; m < 16; m++)
            acc = fmaf(sBe[m], sCw[m * 2 + 1] - sCw[m * 2], acc);
        d_P[224] = acc * LOG2E;
    } else if (t < 229) {                       // pb
        d_P[230 + (t - 225)] = proj_b[t - 225];
    } else if (t < 245) {                       // zero accumulators (replay-safe)
        d_acc[t - 229] = 0.0;
    } else if (t == 245) {
        d_count = 0u;
    }
}

// ================= main: R1's proven scalar loop + cheap-math tweaks =================
__global__ __launch_bounds__(256) void moe_main_kernel(
    const float4* __restrict__ x4, float4* __restrict__ o4,
    float* __restrict__ out, int n, int out_size)
{
    __shared__ alignas(16) float P[256];
    __shared__ float red[8][16];
    __shared__ unsigned s_last;

    const int t = threadIdx.x;
    if (t < 64) ((float4*)P)[t] = ((const float4*)d_P)[t];
    __syncthreads();

    float S[8]  = {0.f, 0.f, 0.f, 0.f, 0.f, 0.f, 0.f, 0.f};
    unsigned cnt = 0;     // nibble counters, tokens/thread <= 15

    const int stride = blockDim.x * gridDim.x;
    #pragma unroll 2
    for (int i = blockIdx.x * blockDim.x + t; i < n; i += stride) {
        const float4 xv = x4[i];

        // gate logits (log2 domain; coeffs prescaled)
        float lg[8];
        #pragma unroll
        for (int e = 0; e < 8; e++)
            lg[e] = fmaf(xv.w, P[24 + e],
                    fmaf(xv.z, P[16 + e],
                    fmaf(xv.y, P[ 8 + e],
                    fmaf(xv.x, P[ 0 + e], P[32 + e]))));

        // first-max argmax (matches jnp.argmax; positive scaling preserves order)
        float m = lg[0]; int idx = 0;
        #pragma unroll
        for (int e = 1; e < 8; e++)
            if (lg[e] > m) { m = lg[e]; idx = e; }

        // softmax probs via raw ex2
        float p[8], sum = 0.f;
        #pragma unroll
        for (int e = 0; e < 8; e++) { p[e] = ex2(lg[e] - m); sum += p[e]; }
        const float inv = __fdividef(1.f, sum);   // == gates[idx]
        #pragma unroll
        for (int e = 0; e < 8; e++) S[e] = fmaf(p[e], inv, S[e]);
        cnt += 1u << (idx << 2);

        // 2-way combine softmax == sigmoid of differenced form (log2 domain)
        const float dl = fmaf(xv.w, P[223], fmaf(xv.z, P[222],
                         fmaf(xv.y, P[221], fmaf(xv.x, P[220], P[224]))));
        const float cw0 = __fdividef(1.f, 1.f + ex2(dl));
        const float cw1 = 1.f - cw0;
        const float a   = cw0 * inv;

        // expert (stride-20 shared block) + residual, both pre-folded thru proj
        const int eo = 40 + idx * 20;
        float4 o;
        float* op = (float*)&o;
        #pragma unroll
        for (int j = 0; j < 4; j++) {
            float ev = fmaf(xv.w, P[eo + 12 + j],
                       fmaf(xv.z, P[eo +  8 + j],
                       fmaf(xv.y, P[eo +  4 + j],
                       fmaf(xv.x, P[eo +      j], P[eo + 16 + j]))));
            float rv = fmaf(xv.w, P[212 + j],
                       fmaf(xv.z, P[208 + j],
                       fmaf(xv.y, P[204 + j],
                       fmaf(xv.x, P[200 + j], P[216 + j]))));
            op[j] = fmaf(a, ev, fmaf(cw1, rv, P[230 + j]));
        }
        o4[i] = o;
    }

    // ---- aux reduction: warp -> block -> global ----
    float Cf[8];
    #pragma unroll
    for (int e = 0; e < 8; e++) Cf[e] = (float)((cnt >> (e << 2)) & 0xFu);

    #pragma unroll
    for (int e = 0; e < 8; e++) {
        #pragma unroll
        for (int off = 16; off; off >>= 1) {
            S[e]  += __shfl_down_sync(0xffffffffu, S[e],  off);
            Cf[e] += __shfl_down_sync(0xffffffffu, Cf[e], off);
        }
    }
    const int lane = t & 31, w = t >> 5;
    if (lane == 0) {
        #pragma unroll
        for (int e = 0; e < 8; e++) { red[w][e] = S[e]; red[w][8 + e] = Cf[e]; }
    }
    __syncthreads();
    if (t < 16) {
        float v = 0.f;
        #pragma unroll
        for (int w2 = 0; w2 < 8; w2++) v += red[w2][t];
        atomicAdd(&d_acc[t], (double)v);
        __threadfence();
    }
    __syncthreads();

    // ---- last-block finalize (graph-replay-safe reset) ----
    if (t == 0) {
        unsigned old = atomicAdd(&d_count, 1u);
        s_last = (old == gridDim.x - 1) ? 1u : 0u;
    }
    __syncthreads();
    if (s_last && t == 0) {
        volatile double* acc = d_acc;
        double s = 0.0;
        #pragma unroll
        for (int e = 0; e < 8; e++) s += acc[e] * acc[8 + e];
        if (out_size > n * 4) {
            const double dn = (double)n;
            out[n * 4] = (float)(8.0 * s / (dn * dn));
        }
        #pragma unroll
        for (int k = 0; k < 16; k++) acc[k] = 0.0;
        __threadfence();
        d_count = 0u;
    }
}

extern "C" void kernel_launch(void* const* d_in, const int* in_sizes, int n_in,
                              void* d_out, int out_size)
{
    const float* x        = (const float*)d_in[0];
    const float* w_embed  = (const float*)d_in[1];
    const float* b_embed  = (const float*)d_in[2];
    const float* gate_w   = (const float*)d_in[3];
    const float* expert_w = (const float*)d_in[4];
    const float* expert_b = (const float*)d_in[5];
    const float* resid_w  = (const float*)d_in[6];
    const float* resid_b  = (const float*)d_in[7];
    const float* comb_w   = (const float*)d_in[8];
    const float* comb_b   = (const float*)d_in[9];
    const float* proj_w   = (const float*)d_in[10];
    const float* proj_b   = (const float*)d_in[11];

    const int n = in_sizes[0] / 4;          // tokens

    setup_kernel<<<1, 256>>>(w_embed, b_embed, gate_w, expert_w, expert_b,
                             resid_w, resid_b, comb_w, comb_b, proj_w, proj_b);

    // R1-proven shape: 8 tokens/thread (nibble-safe <= 15)
    int grid = (n + 256 * 8 - 1) / (256 * 8);
    int min_grid = (n + 256 * 15 - 1) / (256 * 15);
    if (grid < min_grid) grid = min_grid;
    if (grid < 1) grid = 1;

    moe_main_kernel<<<grid, 256>>>((const float4*)x, (float4*)d_out,
                                   (float*)d_out, n, out_size);
}

// round 7
// speedup vs baseline: 1.4721x; 1.0015x over previous
#include <cuda_runtime.h>

__device__ __forceinline__ float ex2(float x) {
    float r; asm("ex2.approx.ftz.f32 %0,%1;" : "=f"(r) : "f"(x)); return r;
}

#define LOG2E 1.4426950408889634f

// ---- folded-parameter layout in d_P / P[256] ----
// [0..32)    G    gate weights [i*8+e]   (log2e-prescaled)
// [32..40)   gb   gate bias              (log2e-prescaled)
// [40..200)  E    per-expert 20: [e*20 + i*4 + j]=EP(4x4), [e*20+16+j]=epb
// [200..216) RP   resid folded thru proj [i*4+j]
// [216..220) rpb
// [220..224) dC   differenced combine    (log2e-prescaled)
// [224]      dcb                         (log2e-prescaled)
// [230..234) pb   proj bias
__device__ alignas(16) float d_P[256];
__device__ double           d_acc[16];   // [0..8) prob sums, [8..16) argmax counts

// ================= setup: float4-staged weights, direct folds (proven ~1us) =================
__global__ __launch_bounds__(256) void setup_kernel(
    const float* __restrict__ w_embed,  const float* __restrict__ b_embed,
    const float* __restrict__ gate_w,   const float* __restrict__ expert_w,
    const float* __restrict__ expert_b, const float* __restrict__ resid_w,
    const float* __restrict__ resid_b,  const float* __restrict__ comb_w,
    const float* __restrict__ comb_b,   const float* __restrict__ proj_w,
    const float* __restrict__ proj_b)
{
    __shared__ float sE[2048];   // expert_w [e*256 + m*16 + k]
    __shared__ float sR[256];    // resid_w  [m*16+k]
    __shared__ float sG[128];    // gate_w   [m*8+e]
    __shared__ float sW[64];     // w_embed  [i*16+m]
    __shared__ float sPj[64];    // proj_w   [k*4+j]
    __shared__ float sEb[128];   // expert_b [e*16+k]
    __shared__ float sBe[16];    // b_embed
    __shared__ float sRb[16];    // resid_b
    __shared__ float sCw[32];    // comb_w   [m*2+c]

    const int t = threadIdx.x;

    {
        const float4* s = (const float4*)expert_w;
        float4* d = (float4*)sE;
        d[t] = s[t];
        d[t + 256] = s[t + 256];
    }
    if (t < 64)       ((float4*)sR)[t]        = ((const float4*)resid_w)[t];
    else if (t < 96)  ((float4*)sG)[t - 64]   = ((const float4*)gate_w)[t - 64];
    else if (t < 112) ((float4*)sW)[t - 96]   = ((const float4*)w_embed)[t - 96];
    else if (t < 128) ((float4*)sPj)[t - 112] = ((const float4*)proj_w)[t - 112];
    else if (t < 160) ((float4*)sEb)[t - 128] = ((const float4*)expert_b)[t - 128];
    else if (t < 164) ((float4*)sBe)[t - 160] = ((const float4*)b_embed)[t - 160];
    else if (t < 168) ((float4*)sRb)[t - 164] = ((const float4*)resid_b)[t - 164];
    else if (t < 176) ((float4*)sCw)[t - 168] = ((const float4*)comb_w)[t - 168];
    __syncthreads();

    if (t < 128) {                              // EP[e][i][j]
        int e = t >> 4, i = (t >> 2) & 3, j = t & 3;
        float acc = 0.f;
        #pragma unroll
        for (int k = 0; k < 16; k++) {
            float tmp = 0.f;
            #pragma unroll
            for (int m = 0; m < 16; m++)
                tmp = fmaf(sW[i * 16 + m], sE[e * 256 + m * 16 + k], tmp);
            acc = fmaf(tmp, sPj[k * 4 + j], acc);
        }
        d_P[40 + e * 20 + i * 4 + j] = acc;
    } else if (t < 160) {                       // epb[e][j]
        int u = t - 128, e = u >> 2, j = u & 3;
        float acc = 0.f;
        #pragma unroll
        for (int k = 0; k < 16; k++) {
            float tmp = sEb[e * 16 + k];
            #pragma unroll
            for (int m = 0; m < 16; m++)
                tmp = fmaf(sBe[m], sE[e * 256 + m * 16 + k], tmp);
            acc = fmaf(tmp, sPj[k * 4 + j], acc);
        }
        d_P[40 + e * 20 + 16 + j] = acc;
    } else if (t < 176) {                       // RP[i][j]
        int u = t - 160, i = u >> 2, j = u & 3;
        float acc = 0.f;
        #pragma unroll
        for (int k = 0; k < 16; k++) {
            float tmp = 0.f;
            #pragma unroll
            for (int m = 0; m < 16; m++)
                tmp = fmaf(sW[i * 16 + m], sR[m * 16 + k], tmp);
            acc = fmaf(tmp, sPj[k * 4 + j], acc);
        }
        d_P[200 + i * 4 + j] = acc;
    } else if (t < 180) {                       // rpb[j]
        int j = t - 176;
        float acc = 0.f;
        #pragma unroll
        for (int k = 0; k < 16; k++) {
            float tmp = sRb[k];
            #pragma unroll
            for (int m = 0; m < 16; m++)
                tmp = fmaf(sBe[m], sR[m * 16 + k], tmp);
            acc = fmaf(tmp, sPj[k * 4 + j], acc);
        }
        d_P[216 + j] = acc;
    } else if (t < 212) {                       // gate W (log2e)
        int u = t - 180, i = u >> 3, e = u & 7;
        float acc = 0.f;
        #pragma unroll
        for (int m = 0; m < 16; m++)
            acc = fmaf(sW[i * 16 + m], sG[m * 8 + e], acc);
        d_P[i * 8 + e] = acc * LOG2E;
    } else if (t < 220) {                       // gate b (log2e)
        int e = t - 212;
        float acc = 0.f;
        #pragma unroll
        for (int m = 0; m < 16; m++)
            acc = fmaf(sBe[m], sG[m * 8 + e], acc);
        d_P[32 + e] = acc * LOG2E;
    } else if (t < 224) {                       // dC (log2e)
        int i = t - 220;
        float acc = 0.f;
        #pragma unroll
        for (int m = 0; m < 16; m++)
            acc = fmaf(sW[i * 16 + m], sCw[m * 2 + 1] - sCw[m * 2], acc);
        d_P[220 + i] = acc * LOG2E;
    } else if (t == 224) {                      // dcb (log2e)
        float acc = comb_b[1] - comb_b[0];
        #pragma unroll
        for (int m = 0; m < 16; m++)
            acc = fmaf(sBe[m], sCw[m * 2 + 1] - sCw[m * 2], acc);
        d_P[224] = acc * LOG2E;
    } else if (t < 229) {                       // pb
        d_P[230 + (t - 225)] = proj_b[t - 225];
    } else if (t < 245) {                       // zero accumulators (replay-safe)
        d_acc[t - 229] = 0.0;
    }
}

// ================= main: R1's loop verbatim (NO unroll, no cap) + cheap math =================
__global__ __launch_bounds__(256) void moe_main_kernel(
    const float4* __restrict__ x4, float4* __restrict__ o4, int n)
{
    __shared__ alignas(16) float P[256];
    __shared__ float red[8][16];

    const int t = threadIdx.x;
    if (t < 64) ((float4*)P)[t] = ((const float4*)d_P)[t];
    __syncthreads();

    float S[8]  = {0.f, 0.f, 0.f, 0.f, 0.f, 0.f, 0.f, 0.f};
    unsigned cnt = 0;     // nibble counters, tokens/thread <= 15

    const int stride = blockDim.x * gridDim.x;
    for (int i = blockIdx.x * blockDim.x + t; i < n; i += stride) {
        const float4 xv = x4[i];

        // gate logits (log2 domain; coeffs prescaled)
        float lg[8];
        #pragma unroll
        for (int e = 0; e < 8; e++)
            lg[e] = fmaf(xv.w, P[24 + e],
                    fmaf(xv.z, P[16 + e],
                    fmaf(xv.y, P[ 8 + e],
                    fmaf(xv.x, P[ 0 + e], P[32 + e]))));

        // first-max argmax (matches jnp.argmax; positive scaling preserves order)
        float m = lg[0]; int idx = 0;
        #pragma unroll
        for (int e = 1; e < 8; e++)
            if (lg[e] > m) { m = lg[e]; idx = e; }

        // softmax probs via raw ex2
        float p[8], sum = 0.f;
        #pragma unroll
        for (int e = 0; e < 8; e++) { p[e] = ex2(lg[e] - m); sum += p[e]; }
        const float inv = __fdividef(1.f, sum);   // == gates[idx]
        #pragma unroll
        for (int e = 0; e < 8; e++) S[e] = fmaf(p[e], inv, S[e]);
        cnt += 1u << (idx << 2);

        // 2-way combine softmax == sigmoid of differenced form (log2 domain)
        const float dl = fmaf(xv.w, P[223], fmaf(xv.z, P[222],
                         fmaf(xv.y, P[221], fmaf(xv.x, P[220], P[224]))));
        const float cw0 = __fdividef(1.f, 1.f + ex2(dl));
        const float cw1 = 1.f - cw0;
        const float a   = cw0 * inv;

        // expert (stride-20 shared block) + residual, both pre-folded thru proj
        const int eo = 40 + idx * 20;
        float4 o;
        float* op = (float*)&o;
        #pragma unroll
        for (int j = 0; j < 4; j++) {
            float ev = fmaf(xv.w, P[eo + 12 + j],
                       fmaf(xv.z, P[eo +  8 + j],
                       fmaf(xv.y, P[eo +  4 + j],
                       fmaf(xv.x, P[eo +      j], P[eo + 16 + j]))));
            float rv = fmaf(xv.w, P[212 + j],
                       fmaf(xv.z, P[208 + j],
                       fmaf(xv.y, P[204 + j],
                       fmaf(xv.x, P[200 + j], P[216 + j]))));
            op[j] = fmaf(a, ev, fmaf(cw1, rv, P[230 + j]));
        }
        o4[i] = o;
    }

    // ---- aux reduction: warp -> block -> global double atomics ----
    float Cf[8];
    #pragma unroll
    for (int e = 0; e < 8; e++) Cf[e] = (float)((cnt >> (e << 2)) & 0xFu);

    #pragma unroll
    for (int e = 0; e < 8; e++) {
        #pragma unroll
        for (int off = 16; off; off >>= 1) {
            S[e]  += __shfl_down_sync(0xffffffffu, S[e],  off);
            Cf[e] += __shfl_down_sync(0xffffffffu, Cf[e], off);
        }
    }
    const int lane = t & 31, w = t >> 5;
    if (lane == 0) {
        #pragma unroll
        for (int e = 0; e < 8; e++) { red[w][e] = S[e]; red[w][8 + e] = Cf[e]; }
    }
    __syncthreads();
    if (t < 16) {
        float v = 0.f;
        #pragma unroll
        for (int w2 = 0; w2 < 8; w2++) v += red[w2][t];
        atomicAdd(&d_acc[t], (double)v);
    }
}

// ================= finalize (separate tiny kernel, as in R1) =================
__global__ void finalize_kernel(float* __restrict__ out, int n, int out_size)
{
    if (threadIdx.x == 0 && out_size > n * 4) {
        double s = 0.0;
        #pragma unroll
        for (int e = 0; e < 8; e++) s += d_acc[e] * d_acc[8 + e];
        const double dn = (double)n;
        out[n * 4] = (float)(8.0 * s / (dn * dn));
    }
}

extern "C" void kernel_launch(void* const* d_in, const int* in_sizes, int n_in,
                              void* d_out, int out_size)
{
    const float* x        = (const float*)d_in[0];
    const float* w_embed  = (const float*)d_in[1];
    const float* b_embed  = (const float*)d_in[2];
    const float* gate_w   = (const float*)d_in[3];
    const float* expert_w = (const float*)d_in[4];
    const float* expert_b = (const float*)d_in[5];
    const float* resid_w  = (const float*)d_in[6];
    const float* resid_b  = (const float*)d_in[7];
    const float* comb_w   = (const float*)d_in[8];
    const float* comb_b   = (const float*)d_in[9];
    const float* proj_w   = (const float*)d_in[10];
    const float* proj_b   = (const float*)d_in[11];

    const int n = in_sizes[0] / 4;          // tokens

    setup_kernel<<<1, 256>>>(w_embed, b_embed, gate_w, expert_w, expert_b,
                             resid_w, resid_b, comb_w, comb_b, proj_w, proj_b);

    // R1 shape: 8 tokens/thread at n=1M (nibble-safe <= 15)
    int grid = (n + 256 * 8 - 1) / (256 * 8);
    int min_grid = (n + 256 * 15 - 1) / (256 * 15);
    if (grid < min_grid) grid = min_grid;
    if (grid < 1) grid = 1;

    moe_main_kernel<<<grid, 256>>>((const float4*)x, (float4*)d_out, n);

    finalize_kernel<<<1, 32>>>((float*)d_out, n, out_size);
}